// round 3
// baseline (speedup 1.0000x reference)
#include <cuda_runtime.h>

#define NN 500000
#define NE 1000000
#define NG 512

#define SCAN_BS 256
#define SCAN_ELEMS 2048                       // 256 threads * 8
#define SCAN_NBLK ((NN + SCAN_ELEMS - 1) / SCAN_ELEMS)   // 245

// ---------------- scratch ----------------
__device__ int    g_cnt_out[NN];
__device__ int    g_cnt_in [NN];
__device__ int    g_row_off[NN + 1];
__device__ int    g_cursor [NN];
__device__ int    g_csr_src[NE];
__device__ int    g_bsum [256];
__device__ int    g_bpref[256];
__device__ float4 g_x [NN * 4];    // [N,16] embed*norm_src
__device__ float4 g_h1[NN * 8];    // [N,32]
__device__ float4 g_hp[NN * 8];    // [N,32] relu(h1@Wpool+bpool)
__device__ float4 g_h2[NN * 16];   // [N,64] relu(h1@Wself + hn@Wneigh + bneigh)

// ---------------- f32x2 helpers ----------------
__device__ __forceinline__ unsigned long long pack2(float a) {
    unsigned long long r;
    asm("mov.b64 %0, {%1, %1};" : "=l"(r) : "f"(a));
    return r;
}
__device__ __forceinline__ void fma2(unsigned long long& d,
                                     unsigned long long a, unsigned long long b) {
    asm("fma.rn.f32x2 %0, %1, %2, %0;" : "+l"(d) : "l"(a), "l"(b));
}
__device__ __forceinline__ float2 unpack2(unsigned long long v) {
    float2 f;
    asm("mov.b64 {%0, %1}, %2;" : "=f"(f.x), "=f"(f.y) : "l"(v));
    return f;
}

// ---------------- init ----------------
__global__ void k_init(float* __restrict__ out) {
    int i = blockIdx.x * blockDim.x + threadIdx.x;
    if (i < NN) { g_cnt_out[i] = 0; g_cnt_in[i] = 0; }
    if (i < NG * 64) out[i] = 0.f;
}

// ---------------- degree counts ----------------
__global__ void k_deg(const int* __restrict__ src, const int* __restrict__ dst) {
    int e = blockIdx.x * blockDim.x + threadIdx.x;
    if (e < NE) {
        atomicAdd(&g_cnt_out[src[e]], 1);
        atomicAdd(&g_cnt_in [dst[e]], 1);
    }
}

// ---------------- scan pass 1 ----------------
__global__ __launch_bounds__(SCAN_BS) void k_scan_bsum() {
    __shared__ int sred[SCAN_BS];
    int b = blockIdx.x, t = threadIdx.x;
    int base = b * SCAN_ELEMS + t * 8;
    int s = 0;
#pragma unroll
    for (int k = 0; k < 8; k++) {
        int idx = base + k;
        if (idx < NN) s += g_cnt_in[idx];
    }
    sred[t] = s;
    __syncthreads();
    for (int o = SCAN_BS / 2; o > 0; o >>= 1) {
        if (t < o) sred[t] += sred[t + o];
        __syncthreads();
    }
    if (t == 0) g_bsum[b] = sred[0];
}

// ---------------- scan pass 2 ----------------
__global__ __launch_bounds__(SCAN_BS) void k_scan_top() {
    __shared__ int s[SCAN_BS];
    int t = threadIdx.x;
    int v = (t < SCAN_NBLK) ? g_bsum[t] : 0;
    s[t] = v;
    __syncthreads();
    for (int o = 1; o < SCAN_BS; o <<= 1) {
        int u = (t >= o) ? s[t - o] : 0;
        __syncthreads();
        s[t] += u;
        __syncthreads();
    }
    if (t < SCAN_NBLK) g_bpref[t] = s[t] - v;
    if (t == 0) g_row_off[NN] = NE;
}

// ---------------- scan pass 3 ----------------
__global__ __launch_bounds__(SCAN_BS) void k_scan_write() {
    __shared__ int sth[SCAN_BS];
    int b = blockIdx.x, t = threadIdx.x;
    int base = b * SCAN_ELEMS + t * 8;
    int vals[8];
    int s = 0;
#pragma unroll
    for (int k = 0; k < 8; k++) {
        int idx = base + k;
        vals[k] = (idx < NN) ? g_cnt_in[idx] : 0;
        s += vals[k];
    }
    sth[t] = s;
    __syncthreads();
    int incl = s;
    for (int o = 1; o < SCAN_BS; o <<= 1) {
        int u = (t >= o) ? sth[t - o] : 0;
        __syncthreads();
        incl += u;
        sth[t] = incl;
        __syncthreads();
    }
    int run = g_bpref[b] + incl - s;
#pragma unroll
    for (int k = 0; k < 8; k++) {
        int idx = base + k;
        if (idx < NN) { g_row_off[idx] = run; g_cursor[idx] = run; }
        run += vals[k];
    }
}

// ---------------- CSR fill ----------------
__global__ void k_fill(const int* __restrict__ src, const int* __restrict__ dst) {
    int e = blockIdx.x * blockDim.x + threadIdx.x;
    if (e < NE) {
        int p = atomicAdd(&g_cursor[dst[e]], 1);
        g_csr_src[p] = src[e];
    }
}

// ---------------- x = embed[tokens] * norm_src ----------------
__global__ void k_embed(const int* __restrict__ tokens, const float* __restrict__ embed) {
    int i = blockIdx.x * blockDim.x + threadIdx.x;
    if (i < NN) {
        float ns = rsqrtf(fmaxf((float)g_cnt_out[i], 1.0f));
        const float4* er = (const float4*)(embed + (long)tokens[i] * 16);
#pragma unroll
        for (int k = 0; k < 4; k++) {
            float4 v = er[k];
            v.x *= ns; v.y *= ns; v.z *= ns; v.w *= ns;
            g_x[i * 4 + k] = v;
        }
    }
}

// ---------------- gather-sum + MLP1 + pool MLP ----------------
__global__ __launch_bounds__(256) void k_h1(
    const float* __restrict__ W1, const float* __restrict__ b1,
    const float* __restrict__ Wp, const float* __restrict__ bp)
{
    __shared__ unsigned long long sW1[16 * 16], sWp[32 * 16], sb1[16], sbp[16];
    for (int t = threadIdx.x; t < 16 * 16; t += blockDim.x)
        ((float2*)sW1)[t] = ((const float2*)W1)[t];
    for (int t = threadIdx.x; t < 32 * 16; t += blockDim.x)
        ((float2*)sWp)[t] = ((const float2*)Wp)[t];
    for (int t = threadIdx.x; t < 16; t += blockDim.x) {
        ((float2*)sb1)[t] = ((const float2*)b1)[t];
        ((float2*)sbp)[t] = ((const float2*)bp)[t];
    }
    __syncthreads();

    int i = blockIdx.x * blockDim.x + threadIdx.x;
    if (i >= NN) return;

    int beg = g_row_off[i], end = g_row_off[i + 1];
    float4 a0 = make_float4(0, 0, 0, 0), a1 = a0, a2 = a0, a3 = a0;
    for (int e = beg; e < end; e++) {
        const float4* xr = &g_x[(size_t)g_csr_src[e] * 4];
        float4 v0 = xr[0], v1 = xr[1], v2 = xr[2], v3 = xr[3];
        a0.x += v0.x; a0.y += v0.y; a0.z += v0.z; a0.w += v0.w;
        a1.x += v1.x; a1.y += v1.y; a1.z += v1.z; a1.w += v1.w;
        a2.x += v2.x; a2.y += v2.y; a2.z += v2.z; a2.w += v2.w;
        a3.x += v3.x; a3.y += v3.y; a3.z += v3.z; a3.w += v3.w;
    }
    float nd = rsqrtf(fmaxf((float)(end - beg), 1.0f));
    float mr[16] = {a0.x * nd, a0.y * nd, a0.z * nd, a0.w * nd,
                    a1.x * nd, a1.y * nd, a1.z * nd, a1.w * nd,
                    a2.x * nd, a2.y * nd, a2.z * nd, a2.w * nd,
                    a3.x * nd, a3.y * nd, a3.z * nd, a3.w * nd};

    unsigned long long acc[16];
#pragma unroll
    for (int j = 0; j < 16; j++) acc[j] = sb1[j];
#pragma unroll
    for (int k = 0; k < 16; k++) {
        unsigned long long av = pack2(mr[k]);
#pragma unroll
        for (int j = 0; j < 16; j++) fma2(acc[j], av, sW1[k * 16 + j]);
    }
    float h1f[32];
#pragma unroll
    for (int j = 0; j < 16; j++) {
        float2 f = unpack2(acc[j]);
        h1f[2 * j] = fmaxf(f.x, 0.f); h1f[2 * j + 1] = fmaxf(f.y, 0.f);
    }
#pragma unroll
    for (int k = 0; k < 8; k++)
        g_h1[i * 8 + k] = make_float4(h1f[4 * k], h1f[4 * k + 1], h1f[4 * k + 2], h1f[4 * k + 3]);

    unsigned long long pcc[16];
#pragma unroll
    for (int j = 0; j < 16; j++) pcc[j] = sbp[j];
#pragma unroll
    for (int k = 0; k < 32; k++) {
        unsigned long long av = pack2(h1f[k]);
#pragma unroll
        for (int j = 0; j < 16; j++) fma2(pcc[j], av, sWp[k * 16 + j]);
    }
#pragma unroll
    for (int j = 0; j < 8; j++) {
        float2 f0 = unpack2(pcc[2 * j]), f1 = unpack2(pcc[2 * j + 1]);
        g_hp[i * 8 + j] = make_float4(fmaxf(f0.x, 0.f), fmaxf(f0.y, 0.f),
                                      fmaxf(f1.x, 0.f), fmaxf(f1.y, 0.f));
    }
}

// ---------------- gather-max + SAGE layer -> g_h2 ----------------
__global__ __launch_bounds__(256) void k_h2(
    const float* __restrict__ Wself, const float* __restrict__ Wneigh,
    const float* __restrict__ bneigh)
{
    __shared__ unsigned long long sWs[32 * 32], sWn[32 * 32], sbn[32];
    for (int t = threadIdx.x; t < 32 * 32; t += blockDim.x) {
        ((float2*)sWs)[t] = ((const float2*)Wself)[t];
        ((float2*)sWn)[t] = ((const float2*)Wneigh)[t];
    }
    for (int t = threadIdx.x; t < 32; t += blockDim.x)
        ((float2*)sbn)[t] = ((const float2*)bneigh)[t];
    __syncthreads();

    int i = blockIdx.x * blockDim.x + threadIdx.x;
    if (i >= NN) return;

    float hnf[32];
#pragma unroll
    for (int j = 0; j < 32; j++) hnf[j] = 0.f;
    int beg = g_row_off[i], end = g_row_off[i + 1];
    for (int e = beg; e < end; e++) {
        const float4* hr = &g_hp[(size_t)g_csr_src[e] * 8];
#pragma unroll
        for (int k = 0; k < 8; k++) {
            float4 v = hr[k];
            hnf[4 * k + 0] = fmaxf(hnf[4 * k + 0], v.x);
            hnf[4 * k + 1] = fmaxf(hnf[4 * k + 1], v.y);
            hnf[4 * k + 2] = fmaxf(hnf[4 * k + 2], v.z);
            hnf[4 * k + 3] = fmaxf(hnf[4 * k + 3], v.w);
        }
    }

    float af[32];
#pragma unroll
    for (int k = 0; k < 8; k++) {
        float4 v = g_h1[(size_t)i * 8 + k];
        af[4 * k + 0] = v.x; af[4 * k + 1] = v.y; af[4 * k + 2] = v.z; af[4 * k + 3] = v.w;
    }

    // two halves of 16 packed accumulators (32 outputs each)
#pragma unroll
    for (int half = 0; half < 2; half++) {
        unsigned long long acc[16];
#pragma unroll
        for (int j = 0; j < 16; j++) acc[j] = sbn[half * 16 + j];
#pragma unroll
        for (int k = 0; k < 32; k++) {
            unsigned long long av = pack2(af[k]);
            unsigned long long bv = pack2(hnf[k]);
#pragma unroll
            for (int j = 0; j < 16; j++) {
                fma2(acc[j], av, sWs[k * 32 + half * 16 + j]);
                fma2(acc[j], bv, sWn[k * 32 + half * 16 + j]);
            }
        }
#pragma unroll
        for (int j = 0; j < 8; j++) {
            float2 f0 = unpack2(acc[2 * j]), f1 = unpack2(acc[2 * j + 1]);
            g_h2[(size_t)i * 16 + half * 8 + j] =
                make_float4(fmaxf(f0.x, 0.f), fmaxf(f0.y, 0.f),
                            fmaxf(f1.x, 0.f), fmaxf(f1.y, 0.f));
        }
    }
}

// ---------------- final linear + graph pooling ----------------
__global__ __launch_bounds__(256) void k_out2(
    const int* __restrict__ graph_ids,
    const float* __restrict__ Wlin, const float* __restrict__ blin,
    float* __restrict__ out)
{
    __shared__ unsigned long long sWl[64 * 32], sbl[32];
    for (int t = threadIdx.x; t < 64 * 32; t += blockDim.x)
        ((float2*)sWl)[t] = ((const float2*)Wlin)[t];
    for (int t = threadIdx.x; t < 32; t += blockDim.x)
        ((float2*)sbl)[t] = ((const float2*)blin)[t];
    __syncthreads();

    int i = blockIdx.x * blockDim.x + threadIdx.x;
    bool valid = i < NN;
    int ic = valid ? i : NN - 1;
    int gid = graph_ids[ic];

    float h2[64];
#pragma unroll
    for (int k = 0; k < 16; k++) {
        float4 v = g_h2[(size_t)ic * 16 + k];
        h2[4 * k + 0] = v.x; h2[4 * k + 1] = v.y; h2[4 * k + 2] = v.z; h2[4 * k + 3] = v.w;
    }

    int lane = threadIdx.x & 31;
    int g0 = __shfl_sync(0xffffffffu, gid, 0);
    bool uni = __all_sync(0xffffffffu, gid == g0);

#pragma unroll
    for (int half = 0; half < 2; half++) {
        unsigned long long acc[16];
#pragma unroll
        for (int j = 0; j < 16; j++) acc[j] = sbl[half * 16 + j];
#pragma unroll
        for (int k = 0; k < 64; k++) {
            unsigned long long av = pack2(h2[k]);
#pragma unroll
            for (int j = 0; j < 16; j++)
                fma2(acc[j], av, sWl[k * 32 + half * 16 + j]);
        }
        float h3h[32];
#pragma unroll
        for (int j = 0; j < 16; j++) {
            float2 f = unpack2(acc[j]);
            h3h[2 * j]     = valid ? fmaxf(f.x, 0.f) : 0.f;
            h3h[2 * j + 1] = valid ? fmaxf(f.y, 0.f) : 0.f;
        }
        if (uni) {
            float o = 0.f;
#pragma unroll
            for (int j = 0; j < 32; j++) {
                float v = h3h[j];
                v += __shfl_xor_sync(0xffffffffu, v, 16);
                v += __shfl_xor_sync(0xffffffffu, v, 8);
                v += __shfl_xor_sync(0xffffffffu, v, 4);
                v += __shfl_xor_sync(0xffffffffu, v, 2);
                v += __shfl_xor_sync(0xffffffffu, v, 1);
                if (lane == j) o = v;
            }
            atomicAdd(out + g0 * 64 + half * 32 + lane, o);
        } else if (valid) {
            float* row = out + gid * 64 + half * 32;
#pragma unroll
            for (int j = 0; j < 32; j++) atomicAdd(row + j, h3h[j]);
        }
    }
}

// ---------------- launch ----------------
extern "C" void kernel_launch(void* const* d_in, const int* in_sizes, int n_in,
                              void* d_out, int out_size) {
    const int*   tokens    = (const int*)  d_in[0];
    const int*   edge_src  = (const int*)  d_in[1];
    const int*   edge_dst  = (const int*)  d_in[2];
    const int*   graph_ids = (const int*)  d_in[3];
    const float* embed     = (const float*)d_in[4];
    const float* W1        = (const float*)d_in[5];
    const float* b1        = (const float*)d_in[6];
    const float* Wpool     = (const float*)d_in[7];
    const float* bpool     = (const float*)d_in[8];
    const float* Wself     = (const float*)d_in[9];
    const float* Wneigh    = (const float*)d_in[10];
    const float* bneigh    = (const float*)d_in[11];
    const float* Wlin      = (const float*)d_in[12];
    const float* blin      = (const float*)d_in[13];
    float* out = (float*)d_out;

    const int TB = 256;
    int gridE = (NE + TB - 1) / TB;
    int gridN = (NN + TB - 1) / TB;

    k_init<<<gridN, TB>>>(out);
    k_deg<<<gridE, TB>>>(edge_src, edge_dst);
    k_scan_bsum <<<SCAN_NBLK, SCAN_BS>>>();
    k_scan_top  <<<1, SCAN_BS>>>();
    k_scan_write<<<SCAN_NBLK, SCAN_BS>>>();
    k_fill<<<gridE, TB>>>(edge_src, edge_dst);
    k_embed<<<gridN, TB>>>(tokens, embed);
    k_h1<<<gridN, TB>>>(W1, b1, Wpool, bpool);
    k_h2<<<gridN, TB>>>(Wself, Wneigh, bneigh);
    k_out2<<<gridN, TB>>>(graph_ids, Wlin, blin, out);
}

// round 4
// speedup vs baseline: 1.0998x; 1.0998x over previous
#include <cuda_runtime.h>

#define NN 500000
#define NE 1000000
#define NG 512

#define SCAN_BS 256
#define SCAN_ELEMS 2048                       // 256 threads * 8
#define SCAN_NBLK ((NN + SCAN_ELEMS - 1) / SCAN_ELEMS)   // 245

typedef unsigned long long u64;

// ---------------- scratch ----------------
__device__ int    g_cnt_out[NN];
__device__ int    g_cnt_in [NN];
__device__ int    g_row_off[NN + 1];
__device__ int    g_cursor [NN];
__device__ int    g_csr_src[NE];
__device__ int    g_bsum [256];
__device__ int    g_bpref[256];
__device__ float4 g_x [NN * 4];    // [N,16] embed*norm_src
__device__ float4 g_h1[NN * 8];    // [N,32]
__device__ float4 g_hp[NN * 8];    // [N,32] relu(h1@Wpool+bpool)

// ---------------- f32x2 helpers ----------------
__device__ __forceinline__ u64 pack2(float a) {
    u64 r;
    asm("mov.b64 %0, {%1, %1};" : "=l"(r) : "f"(a));
    return r;
}
__device__ __forceinline__ void fma2(u64& d, u64 a, u64 b) {
    asm("fma.rn.f32x2 %0, %1, %2, %0;" : "+l"(d) : "l"(a), "l"(b));
}
__device__ __forceinline__ float2 unpack2(u64 v) {
    float2 f;
    asm("mov.b64 {%0, %1}, %2;" : "=f"(f.x), "=f"(f.y) : "l"(v));
    return f;
}

// ---------------- init ----------------
__global__ void k_init(float* __restrict__ out) {
    int i = blockIdx.x * blockDim.x + threadIdx.x;
    if (i < NN) { g_cnt_out[i] = 0; g_cnt_in[i] = 0; }
    if (i < NG * 64) out[i] = 0.f;
}

// ---------------- degree counts ----------------
__global__ void k_deg(const int* __restrict__ src, const int* __restrict__ dst) {
    int e = blockIdx.x * blockDim.x + threadIdx.x;
    if (e < NE) {
        atomicAdd(&g_cnt_out[src[e]], 1);
        atomicAdd(&g_cnt_in [dst[e]], 1);
    }
}

// ---------------- scan pass 1 ----------------
__global__ __launch_bounds__(SCAN_BS) void k_scan_bsum() {
    __shared__ int sred[SCAN_BS];
    int b = blockIdx.x, t = threadIdx.x;
    int base = b * SCAN_ELEMS + t * 8;
    int s = 0;
#pragma unroll
    for (int k = 0; k < 8; k++) {
        int idx = base + k;
        if (idx < NN) s += g_cnt_in[idx];
    }
    sred[t] = s;
    __syncthreads();
    for (int o = SCAN_BS / 2; o > 0; o >>= 1) {
        if (t < o) sred[t] += sred[t + o];
        __syncthreads();
    }
    if (t == 0) g_bsum[b] = sred[0];
}

// ---------------- scan pass 2 ----------------
__global__ __launch_bounds__(SCAN_BS) void k_scan_top() {
    __shared__ int s[SCAN_BS];
    int t = threadIdx.x;
    int v = (t < SCAN_NBLK) ? g_bsum[t] : 0;
    s[t] = v;
    __syncthreads();
    for (int o = 1; o < SCAN_BS; o <<= 1) {
        int u = (t >= o) ? s[t - o] : 0;
        __syncthreads();
        s[t] += u;
        __syncthreads();
    }
    if (t < SCAN_NBLK) g_bpref[t] = s[t] - v;
    if (t == 0) g_row_off[NN] = NE;
}

// ---------------- scan pass 3 ----------------
__global__ __launch_bounds__(SCAN_BS) void k_scan_write() {
    __shared__ int sth[SCAN_BS];
    int b = blockIdx.x, t = threadIdx.x;
    int base = b * SCAN_ELEMS + t * 8;
    int vals[8];
    int s = 0;
#pragma unroll
    for (int k = 0; k < 8; k++) {
        int idx = base + k;
        vals[k] = (idx < NN) ? g_cnt_in[idx] : 0;
        s += vals[k];
    }
    sth[t] = s;
    __syncthreads();
    int incl = s;
    for (int o = 1; o < SCAN_BS; o <<= 1) {
        int u = (t >= o) ? sth[t - o] : 0;
        __syncthreads();
        incl += u;
        sth[t] = incl;
        __syncthreads();
    }
    int run = g_bpref[b] + incl - s;
#pragma unroll
    for (int k = 0; k < 8; k++) {
        int idx = base + k;
        if (idx < NN) { g_row_off[idx] = run; g_cursor[idx] = run; }
        run += vals[k];
    }
}

// ---------------- CSR fill ----------------
__global__ void k_fill(const int* __restrict__ src, const int* __restrict__ dst) {
    int e = blockIdx.x * blockDim.x + threadIdx.x;
    if (e < NE) {
        int p = atomicAdd(&g_cursor[dst[e]], 1);
        g_csr_src[p] = src[e];
    }
}

// ---------------- x = embed[tokens] * norm_src ----------------
__global__ void k_embed(const int* __restrict__ tokens, const float* __restrict__ embed) {
    int i = blockIdx.x * blockDim.x + threadIdx.x;
    if (i < NN) {
        float ns = rsqrtf(fmaxf((float)g_cnt_out[i], 1.0f));
        const float4* er = (const float4*)(embed + (long)tokens[i] * 16);
#pragma unroll
        for (int k = 0; k < 4; k++) {
            float4 v = er[k];
            v.x *= ns; v.y *= ns; v.z *= ns; v.w *= ns;
            g_x[i * 4 + k] = v;
        }
    }
}

// ---------------- gather-sum + MLP1 + pool MLP ----------------
__global__ __launch_bounds__(256) void k_h1(
    const float* __restrict__ W1, const float* __restrict__ b1,
    const float* __restrict__ Wp, const float* __restrict__ bp)
{
    __shared__ __align__(16) u64 sW1[16 * 16], sWp[32 * 16];
    __shared__ u64 sb1[16], sbp[16];
    for (int t = threadIdx.x; t < 16 * 16; t += blockDim.x)
        ((float2*)sW1)[t] = ((const float2*)W1)[t];
    for (int t = threadIdx.x; t < 32 * 16; t += blockDim.x)
        ((float2*)sWp)[t] = ((const float2*)Wp)[t];
    for (int t = threadIdx.x; t < 16; t += blockDim.x) {
        ((float2*)sb1)[t] = ((const float2*)b1)[t];
        ((float2*)sbp)[t] = ((const float2*)bp)[t];
    }
    __syncthreads();

    int i = blockIdx.x * blockDim.x + threadIdx.x;
    if (i >= NN) return;

    int beg = g_row_off[i], end = g_row_off[i + 1];
    float4 a0 = make_float4(0, 0, 0, 0), a1 = a0, a2 = a0, a3 = a0;
    for (int e = beg; e < end; e++) {
        const float4* xr = &g_x[(size_t)g_csr_src[e] * 4];
        float4 v0 = xr[0], v1 = xr[1], v2 = xr[2], v3 = xr[3];
        a0.x += v0.x; a0.y += v0.y; a0.z += v0.z; a0.w += v0.w;
        a1.x += v1.x; a1.y += v1.y; a1.z += v1.z; a1.w += v1.w;
        a2.x += v2.x; a2.y += v2.y; a2.z += v2.z; a2.w += v2.w;
        a3.x += v3.x; a3.y += v3.y; a3.z += v3.z; a3.w += v3.w;
    }
    float nd = rsqrtf(fmaxf((float)(end - beg), 1.0f));
    float mr[16] = {a0.x * nd, a0.y * nd, a0.z * nd, a0.w * nd,
                    a1.x * nd, a1.y * nd, a1.z * nd, a1.w * nd,
                    a2.x * nd, a2.y * nd, a2.z * nd, a2.w * nd,
                    a3.x * nd, a3.y * nd, a3.z * nd, a3.w * nd};

    // h1 = relu(mr @ W1 + b1)
    u64 acc[16];
#pragma unroll
    for (int j = 0; j < 16; j++) acc[j] = sb1[j];
#pragma unroll
    for (int k = 0; k < 16; k++) {
        u64 av = pack2(mr[k]);
        const ulonglong2* pw = (const ulonglong2*)&sW1[k * 16];
#pragma unroll
        for (int jj = 0; jj < 8; jj++) {
            ulonglong2 w = pw[jj];
            fma2(acc[2 * jj], av, w.x);
            fma2(acc[2 * jj + 1], av, w.y);
        }
    }
    float h1f[32];
#pragma unroll
    for (int j = 0; j < 16; j++) {
        float2 f = unpack2(acc[j]);
        h1f[2 * j] = fmaxf(f.x, 0.f); h1f[2 * j + 1] = fmaxf(f.y, 0.f);
    }
#pragma unroll
    for (int k = 0; k < 8; k++)
        g_h1[i * 8 + k] = make_float4(h1f[4 * k], h1f[4 * k + 1], h1f[4 * k + 2], h1f[4 * k + 3]);

    // hp = relu(h1 @ Wpool + bpool)
    u64 pcc[16];
#pragma unroll
    for (int j = 0; j < 16; j++) pcc[j] = sbp[j];
#pragma unroll
    for (int k = 0; k < 32; k++) {
        u64 av = pack2(h1f[k]);
        const ulonglong2* pw = (const ulonglong2*)&sWp[k * 16];
#pragma unroll
        for (int jj = 0; jj < 8; jj++) {
            ulonglong2 w = pw[jj];
            fma2(pcc[2 * jj], av, w.x);
            fma2(pcc[2 * jj + 1], av, w.y);
        }
    }
#pragma unroll
    for (int j = 0; j < 8; j++) {
        float2 f0 = unpack2(pcc[2 * j]), f1 = unpack2(pcc[2 * j + 1]);
        g_hp[i * 8 + j] = make_float4(fmaxf(f0.x, 0.f), fmaxf(f0.y, 0.f),
                                      fmaxf(f1.x, 0.f), fmaxf(f1.y, 0.f));
    }
}

// ---------------- fused: gather-max + SAGE + lin + pooling ----------------
__global__ __launch_bounds__(256) void k_out(
    const int* __restrict__ graph_ids,
    const float* __restrict__ Wself, const float* __restrict__ Wneigh,
    const float* __restrict__ bneigh,
    const float* __restrict__ Wlin, const float* __restrict__ blin,
    float* __restrict__ out)
{
    __shared__ __align__(16) u64 sWs[32 * 32], sWn[32 * 32], sWl[64 * 32];
    __shared__ u64 sbn[32], sbl[32];
    for (int t = threadIdx.x; t < 32 * 32; t += blockDim.x) {
        ((float2*)sWs)[t] = ((const float2*)Wself)[t];
        ((float2*)sWn)[t] = ((const float2*)Wneigh)[t];
    }
    for (int t = threadIdx.x; t < 64 * 32; t += blockDim.x)
        ((float2*)sWl)[t] = ((const float2*)Wlin)[t];
    for (int t = threadIdx.x; t < 32; t += blockDim.x) {
        ((float2*)sbn)[t] = ((const float2*)bneigh)[t];
        ((float2*)sbl)[t] = ((const float2*)blin)[t];
    }
    __syncthreads();

    int i = blockIdx.x * blockDim.x + threadIdx.x;
    bool valid = i < NN;
    int ic = valid ? i : NN - 1;
    int gid = graph_ids[ic];

    // gather-max of hp over incoming edges (hp >= 0; isolated -> 0 matches DGL)
    float hnf[32];
#pragma unroll
    for (int j = 0; j < 32; j++) hnf[j] = 0.f;
    int beg = g_row_off[ic], end = g_row_off[ic + 1];
    for (int e = beg; e < end; e++) {
        const float4* hr = &g_hp[(size_t)g_csr_src[e] * 8];
#pragma unroll
        for (int k = 0; k < 8; k++) {
            float4 v = hr[k];
            hnf[4 * k + 0] = fmaxf(hnf[4 * k + 0], v.x);
            hnf[4 * k + 1] = fmaxf(hnf[4 * k + 1], v.y);
            hnf[4 * k + 2] = fmaxf(hnf[4 * k + 2], v.z);
            hnf[4 * k + 3] = fmaxf(hnf[4 * k + 3], v.w);
        }
    }

    float af[32];
#pragma unroll
    for (int k = 0; k < 8; k++) {
        float4 v = g_h1[(size_t)ic * 8 + k];
        af[4 * k + 0] = v.x; af[4 * k + 1] = v.y; af[4 * k + 2] = v.z; af[4 * k + 3] = v.w;
    }

    // running packed accumulators for h3 (64 outputs)
    u64 h3acc[32];
#pragma unroll
    for (int j = 0; j < 32; j++) h3acc[j] = sbl[j];

    // h2 computed in two 32-wide halves; each half immediately folded into h3acc
#pragma unroll
    for (int half = 0; half < 2; half++) {
        u64 acc[16];
#pragma unroll
        for (int j = 0; j < 16; j++) acc[j] = sbn[half * 16 + j];
#pragma unroll
        for (int k = 0; k < 32; k++) {
            u64 av = pack2(af[k]);
            u64 bv = pack2(hnf[k]);
            const ulonglong2* ps = (const ulonglong2*)&sWs[k * 32 + half * 16];
            const ulonglong2* pn = (const ulonglong2*)&sWn[k * 32 + half * 16];
#pragma unroll
            for (int jj = 0; jj < 8; jj++) {
                ulonglong2 w = ps[jj];
                fma2(acc[2 * jj], av, w.x);
                fma2(acc[2 * jj + 1], av, w.y);
                ulonglong2 u = pn[jj];
                fma2(acc[2 * jj], bv, u.x);
                fma2(acc[2 * jj + 1], bv, u.y);
            }
        }
        float hh[32];
#pragma unroll
        for (int j = 0; j < 16; j++) {
            float2 f = unpack2(acc[j]);
            hh[2 * j] = fmaxf(f.x, 0.f); hh[2 * j + 1] = fmaxf(f.y, 0.f);
        }
        // fold this h2 half into h3acc: k index = half*32 + k2 (order matches full sum)
#pragma unroll
        for (int k2 = 0; k2 < 32; k2++) {
            u64 av = pack2(hh[k2]);
            const ulonglong2* pl = (const ulonglong2*)&sWl[(half * 32 + k2) * 32];
#pragma unroll
            for (int jj = 0; jj < 16; jj++) {
                ulonglong2 w = pl[jj];
                fma2(h3acc[2 * jj], av, w.x);
                fma2(h3acc[2 * jj + 1], av, w.y);
            }
        }
    }

    // graph pooling: graph_ids sorted -> warps almost always uniform
    int lane = threadIdx.x & 31;
    int g0 = __shfl_sync(0xffffffffu, gid, 0);
    bool uni = __all_sync(0xffffffffu, gid == g0);
    if (uni) {
        float o0 = 0.f, o1 = 0.f;
#pragma unroll
        for (int jj = 0; jj < 32; jj++) {
            float2 f = unpack2(h3acc[jj]);
            float v0 = valid ? fmaxf(f.x, 0.f) : 0.f;
            float v1 = valid ? fmaxf(f.y, 0.f) : 0.f;
            v0 += __shfl_xor_sync(0xffffffffu, v0, 16);
            v0 += __shfl_xor_sync(0xffffffffu, v0, 8);
            v0 += __shfl_xor_sync(0xffffffffu, v0, 4);
            v0 += __shfl_xor_sync(0xffffffffu, v0, 2);
            v0 += __shfl_xor_sync(0xffffffffu, v0, 1);
            v1 += __shfl_xor_sync(0xffffffffu, v1, 16);
            v1 += __shfl_xor_sync(0xffffffffu, v1, 8);
            v1 += __shfl_xor_sync(0xffffffffu, v1, 4);
            v1 += __shfl_xor_sync(0xffffffffu, v1, 2);
            v1 += __shfl_xor_sync(0xffffffffu, v1, 1);
            int j0 = 2 * jj, j1 = 2 * jj + 1;
            if (lane == (j0 & 31)) { if (j0 < 32) o0 = v0; else o1 = v0; }
            if (lane == (j1 & 31)) { if (j1 < 32) o0 = v1; else o1 = v1; }
        }
        float* row = out + g0 * 64;
        atomicAdd(row + lane, o0);
        atomicAdd(row + 32 + lane, o1);
    } else if (valid) {
        float* row = out + gid * 64;
#pragma unroll
        for (int jj = 0; jj < 32; jj++) {
            float2 f = unpack2(h3acc[jj]);
            atomicAdd(row + 2 * jj,     fmaxf(f.x, 0.f));
            atomicAdd(row + 2 * jj + 1, fmaxf(f.y, 0.f));
        }
    }
}

// ---------------- launch ----------------
extern "C" void kernel_launch(void* const* d_in, const int* in_sizes, int n_in,
                              void* d_out, int out_size) {
    const int*   tokens    = (const int*)  d_in[0];
    const int*   edge_src  = (const int*)  d_in[1];
    const int*   edge_dst  = (const int*)  d_in[2];
    const int*   graph_ids = (const int*)  d_in[3];
    const float* embed     = (const float*)d_in[4];
    const float* W1        = (const float*)d_in[5];
    const float* b1        = (const float*)d_in[6];
    const float* Wpool     = (const float*)d_in[7];
    const float* bpool     = (const float*)d_in[8];
    const float* Wself     = (const float*)d_in[9];
    const float* Wneigh    = (const float*)d_in[10];
    const float* bneigh    = (const float*)d_in[11];
    const float* Wlin      = (const float*)d_in[12];
    const float* blin      = (const float*)d_in[13];
    float* out = (float*)d_out;

    const int TB = 256;
    int gridE = (NE + TB - 1) / TB;
    int gridN = (NN + TB - 1) / TB;

    k_init<<<gridN, TB>>>(out);
    k_deg<<<gridE, TB>>>(edge_src, edge_dst);
    k_scan_bsum <<<SCAN_NBLK, SCAN_BS>>>();
    k_scan_top  <<<1, SCAN_BS>>>();
    k_scan_write<<<SCAN_NBLK, SCAN_BS>>>();
    k_fill<<<gridE, TB>>>(edge_src, edge_dst);
    k_embed<<<gridN, TB>>>(tokens, embed);
    k_h1<<<gridN, TB>>>(W1, b1, Wpool, bpool);
    k_out<<<gridN, TB>>>(graph_ids, Wself, Wneigh, bneigh, Wlin, blin, out);
}